// round 1
// baseline (speedup 1.0000x reference)
#include <cuda_runtime.h>

#define SS 7
#define NC 20
#define PREDC 30   // NC + 10
#define TGTC  25   // NC + 5
#define BATCH 16384
#define CELLS (BATCH * SS * SS)   // 802816
#define CPB 128                    // cells (=threads) per block
#define NBLK (CELLS / CPB)         // 6272, divides evenly

__device__ __forceinline__ float iou_fn(float ax, float ay, float aw, float ah,
                                        float bx, float by, float bw, float bh) {
    float ax1 = ax - aw * 0.5f, ax2 = ax + aw * 0.5f;
    float ay1 = ay - ah * 0.5f, ay2 = ay + ah * 0.5f;
    float bx1 = bx - bw * 0.5f, bx2 = bx + bw * 0.5f;
    float by1 = by - bh * 0.5f, by2 = by + bh * 0.5f;
    float iw = fminf(ax2, bx2) - fmaxf(ax1, bx1); iw = fmaxf(iw, 0.0f);
    float ih = fminf(ay2, by2) - fmaxf(ay1, by1); ih = fmaxf(ih, 0.0f);
    float inter = iw * ih;
    float area_a = fabsf(aw * ah);
    float area_b = fabsf(bw * bh);
    return inter / (area_a + area_b - inter + 1e-6f);
}

__global__ __launch_bounds__(CPB)
void yolo_loss_kernel(const float* __restrict__ pred,
                      const float* __restrict__ tgt,
                      float* __restrict__ out) {
    __shared__ float sp[CPB * PREDC];   // 15360 B
    __shared__ float st[CPB * TGTC];    // 12800 B
    __shared__ float warp_sums[CPB / 32];

    const long long cell_base = (long long)blockIdx.x * CPB;
    const float* pg = pred + cell_base * PREDC;
    const float* tg = tgt  + cell_base * TGTC;

    // Coalesced staged loads of this block's 128 contiguous cells.
    #pragma unroll 4
    for (int i = threadIdx.x; i < CPB * PREDC; i += CPB) sp[i] = pg[i];
    #pragma unroll 4
    for (int i = threadIdx.x; i < CPB * TGTC; i += CPB) st[i] = tg[i];
    __syncthreads();

    const float* p = sp + threadIdx.x * PREDC;
    const float* t = st + threadIdx.x * TGTC;

    // Class loss: sum over 20 channels.
    float cls = 0.0f;
    #pragma unroll
    for (int c = 0; c < NC; c++) {
        float d = p[c] - t[c];
        cls = fmaf(d, d, cls);
    }

    float b1x = p[20], b1y = p[21], b1w = p[22], b1h = p[23], b1c = p[24];
    float b2x = p[25], b2y = p[26], b2w = p[27], b2h = p[28], b2c = p[29];
    // NOTE: tb = targets[..., C:C+5] -> channels 20..24 (channel 20 is also the obj flag)
    float tx = t[20], ty = t[21], tw = t[22], th = t[23], tc = t[24];
    float obj = (t[20] == 1.0f) ? 1.0f : 0.0f;

    float iou1 = iou_fn(b1x, b1y, b1w, b1h, tx, ty, tw, th);
    float iou2 = iou_fn(b2x, b2y, b2w, b2h, tx, ty, tw, th);
    bool use1 = iou1 > iou2;

    float rx = use1 ? b1x : b2x;
    float ry = use1 ? b1y : b2y;
    float rw = use1 ? b1w : b2w;
    float rh = use1 ? b1h : b2h;
    float rc = use1 ? b1c : b2c;
    float other_conf = use1 ? b2c : b1c;

    float srw = sqrtf(fmaxf(rw, 1e-6f));
    float srh = sqrtf(fmaxf(rh, 1e-6f));
    float stw = sqrtf(fmaxf(tw, 1e-6f));
    float sth = sqrtf(fmaxf(th, 1e-6f));

    float dx = rx - tx, dy = ry - ty, dw = srw - stw, dh = srh - sth;
    float coord = 5.0f * (dx * dx + dy * dy + dw * dw + dh * dh);
    float dc = rc - tc;
    float obj_conf = dc * dc;
    float noobj_in  = 0.5f * other_conf * other_conf;
    float noobj_out = 0.5f * (b1c * b1c + b2c * b2c);

    float loss = obj * (coord + obj_conf + cls + noobj_in)
               + (1.0f - obj) * noobj_out;

    // Warp reduce
    #pragma unroll
    for (int off = 16; off > 0; off >>= 1)
        loss += __shfl_xor_sync(0xFFFFFFFFu, loss, off);

    int lane = threadIdx.x & 31;
    int wid  = threadIdx.x >> 5;
    if (lane == 0) warp_sums[wid] = loss;
    __syncthreads();

    if (threadIdx.x == 0) {
        float s = 0.0f;
        #pragma unroll
        for (int w = 0; w < CPB / 32; w++) s += warp_sums[w];
        atomicAdd(out, s * (1.0f / (float)BATCH));
    }
}

extern "C" void kernel_launch(void* const* d_in, const int* in_sizes, int n_in,
                              void* d_out, int out_size) {
    const float* pred = (const float*)d_in[0];
    const float* tgt  = (const float*)d_in[1];
    float* out = (float*)d_out;
    cudaMemsetAsync(out, 0, sizeof(float));
    yolo_loss_kernel<<<NBLK, CPB>>>(pred, tgt, out);
}

// round 2
// speedup vs baseline: 1.8699x; 1.8699x over previous
#include <cuda_runtime.h>

#define SS 7
#define NC 20
#define PREDC 30   // NC + 10
#define TGTC  25   // NC + 5
#define BATCH 16384
#define CELLS (BATCH * SS * SS)   // 802816
#define CPB 128                    // cells (=threads) per block
#define NBLK (CELLS / CPB)         // 6272, divides evenly

// float4 counts per block tile
#define PF4 (CPB * PREDC / 4)      // 960
#define TF4 (CPB * TGTC / 4)       // 800
#define PF4_FULL (PF4 / CPB)       // 7 full rounds
#define PF4_REM  (PF4 - PF4_FULL * CPB)  // 64
#define TF4_FULL (TF4 / CPB)       // 6 full rounds
#define TF4_REM  (TF4 - TF4_FULL * CPB)  // 32

__device__ __forceinline__ float iou_fn(float ax, float ay, float aw, float ah,
                                        float bx, float by, float bw, float bh) {
    float ax1 = ax - aw * 0.5f, ax2 = ax + aw * 0.5f;
    float ay1 = ay - ah * 0.5f, ay2 = ay + ah * 0.5f;
    float bx1 = bx - bw * 0.5f, bx2 = bx + bw * 0.5f;
    float by1 = by - bh * 0.5f, by2 = by + bh * 0.5f;
    float iw = fminf(ax2, bx2) - fmaxf(ax1, bx1); iw = fmaxf(iw, 0.0f);
    float ih = fminf(ay2, by2) - fmaxf(ay1, by1); ih = fmaxf(ih, 0.0f);
    float inter = iw * ih;
    float area_a = fabsf(aw * ah);
    float area_b = fabsf(bw * bh);
    return inter / (area_a + area_b - inter + 1e-6f);
}

__global__ __launch_bounds__(CPB)
void yolo_loss_kernel(const float* __restrict__ pred,
                      const float* __restrict__ tgt,
                      float* __restrict__ out) {
    __shared__ __align__(16) float sp[CPB * PREDC];   // 15360 B
    __shared__ __align__(16) float st[CPB * TGTC];    // 12800 B
    __shared__ float warp_sums[CPB / 32];

    const long long cell_base = (long long)blockIdx.x * CPB;

    // ---- Vectorized staging: LDG.128 fully unrolled so loads front-batch ----
    const float4* __restrict__ pg4 =
        reinterpret_cast<const float4*>(pred) + cell_base * (PREDC / 2) / 2; // cell_base*30/4
    const float4* __restrict__ tg4 =
        reinterpret_cast<const float4*>(tgt) + cell_base * TGTC / 4;

    float4* sp4 = reinterpret_cast<float4*>(sp);
    float4* st4 = reinterpret_cast<float4*>(st);

    {
        float4 pr[PF4_FULL];
        float4 tr[TF4_FULL];
        float4 prem, trem;
        const int tid = threadIdx.x;

        #pragma unroll
        for (int k = 0; k < PF4_FULL; k++) pr[k] = pg4[tid + k * CPB];
        if (tid < PF4_REM) prem = pg4[tid + PF4_FULL * CPB];
        #pragma unroll
        for (int k = 0; k < TF4_FULL; k++) tr[k] = tg4[tid + k * CPB];
        if (tid < TF4_REM) trem = tg4[tid + TF4_FULL * CPB];

        #pragma unroll
        for (int k = 0; k < PF4_FULL; k++) sp4[tid + k * CPB] = pr[k];
        if (tid < PF4_REM) sp4[tid + PF4_FULL * CPB] = prem;
        #pragma unroll
        for (int k = 0; k < TF4_FULL; k++) st4[tid + k * CPB] = tr[k];
        if (tid < TF4_REM) st4[tid + TF4_FULL * CPB] = trem;
    }
    __syncthreads();

    const float* p = sp + threadIdx.x * PREDC;
    const float* t = st + threadIdx.x * TGTC;

    // Class loss over 20 channels.
    float cls = 0.0f;
    #pragma unroll
    for (int c = 0; c < NC; c++) {
        float d = p[c] - t[c];
        cls = fmaf(d, d, cls);
    }

    float b1x = p[20], b1y = p[21], b1w = p[22], b1h = p[23], b1c = p[24];
    float b2x = p[25], b2y = p[26], b2w = p[27], b2h = p[28], b2c = p[29];
    // tb = targets[..., C:C+5] -> channels 20..24 (channel 20 is also the obj flag)
    float tx = t[20], ty = t[21], tw = t[22], th = t[23], tc = t[24];
    float obj = (t[20] == 1.0f) ? 1.0f : 0.0f;

    float iou1 = iou_fn(b1x, b1y, b1w, b1h, tx, ty, tw, th);
    float iou2 = iou_fn(b2x, b2y, b2w, b2h, tx, ty, tw, th);
    bool use1 = iou1 > iou2;

    float rx = use1 ? b1x : b2x;
    float ry = use1 ? b1y : b2y;
    float rw = use1 ? b1w : b2w;
    float rh = use1 ? b1h : b2h;
    float rc = use1 ? b1c : b2c;
    float other_conf = use1 ? b2c : b1c;

    float srw = sqrtf(fmaxf(rw, 1e-6f));
    float srh = sqrtf(fmaxf(rh, 1e-6f));
    float stw = sqrtf(fmaxf(tw, 1e-6f));
    float sth = sqrtf(fmaxf(th, 1e-6f));

    float dx = rx - tx, dy = ry - ty, dw = srw - stw, dh = srh - sth;
    float coord = 5.0f * (dx * dx + dy * dy + dw * dw + dh * dh);
    float dc = rc - tc;
    float obj_conf = dc * dc;
    float noobj_in  = 0.5f * other_conf * other_conf;
    float noobj_out = 0.5f * (b1c * b1c + b2c * b2c);

    float loss = obj * (coord + obj_conf + cls + noobj_in)
               + (1.0f - obj) * noobj_out;

    // Warp reduce
    #pragma unroll
    for (int off = 16; off > 0; off >>= 1)
        loss += __shfl_xor_sync(0xFFFFFFFFu, loss, off);

    int lane = threadIdx.x & 31;
    int wid  = threadIdx.x >> 5;
    if (lane == 0) warp_sums[wid] = loss;
    __syncthreads();

    if (threadIdx.x == 0) {
        float s = 0.0f;
        #pragma unroll
        for (int w = 0; w < CPB / 32; w++) s += warp_sums[w];
        atomicAdd(out, s * (1.0f / (float)BATCH));
    }
}

extern "C" void kernel_launch(void* const* d_in, const int* in_sizes, int n_in,
                              void* d_out, int out_size) {
    const float* pred = (const float*)d_in[0];
    const float* tgt  = (const float*)d_in[1];
    float* out = (float*)d_out;
    cudaMemsetAsync(out, 0, sizeof(float));
    yolo_loss_kernel<<<NBLK, CPB>>>(pred, tgt, out);
}